// round 17
// baseline (speedup 1.0000x reference)
#include <cuda_runtime.h>
#include <math.h>

// Shapes fixed by reference: [2,4,32,64,64]
constexpr int Cc    = 32;          // channels per tensor
constexpr int HW    = 4096;        // 64*64 positions
constexpr int NI    = 8;           // B*L items
constexpr int TPB   = 128;         // positions per block
constexpr int BPI   = 32;          // blocks per item -> 256 blocks
constexpr int PITCH = 132;         // PITCH % 32 == 4 -> conflict-free fragments
constexpr int TH1   = 256;         // 8 warps
constexpr int NREP  = 8;           // accumulator replicas

// Replicated stacked-Gram accumulators: [replica][item][64*64] = 1 MB.
// Zero at module load; item epilogues re-zero after reading (replay-clean).
__device__ float    g_acc[(size_t)NREP * NI * 4096];
__device__ float    g_item[NI];          // per-item loss partials (overwritten)
__device__ unsigned g_tick[NI + 1];      // per-item tickets + final ticket

__global__ __launch_bounds__(TH1) void k_fused(const float* __restrict__ S,
                                               const float* __restrict__ T,
                                               float* __restrict__ out) {
    // Stacked normalized tile U[64][TPB]: rows 0-31 = T-hat, 32-63 = S-hat.
    __shared__ __align__(16) float sU[64 * PITCH];
    __shared__ __align__(16) float ivv[2][TPB];    // [0]: T norms, [1]: S norms
    __shared__ unsigned s_pos;

    const int n   = blockIdx.y;
    const int blk = blockIdx.x;
    const int tid = threadIdx.x;
    const int p0  = blk * TPB;

    const float4* __restrict__ Sb4 = (const float4*)(S + (size_t)n * Cc * HW);
    const float4* __restrict__ Tb4 = (const float4*)(T + (size_t)n * Cc * HW);

    // ---- Load [2 x 32 x 128] f32 as float4 (coalesced) ----
#pragma unroll
    for (int s = tid; s < 2048; s += TH1) {
        const int tensor = s >> 10;          // 0: T -> rows 0-31, 1: S -> rows 32-63
        const int c = (s >> 5) & 31;
        const int q = s & 31;
        const float4 v = tensor ? Sb4[(size_t)c * (HW / 4) + (p0 >> 2) + q]
                                : Tb4[(size_t)c * (HW / 4) + (p0 >> 2) + q];
        *(float4*)&sU[(tensor * 32 + c) * PITCH + 4 * q] = v;
    }
    __syncthreads();

    // ---- Per-position inverse norms (one thread per (tensor, position)) ----
    {
        const int half = tid >> 7;           // 0: rows 0-31 (T), 1: rows 32-63 (S)
        const int p = tid & 127;
        const float* base = sU + half * 32 * PITCH;
        float s0 = 0.f, s1 = 0.f, s2 = 0.f, s3 = 0.f;
#pragma unroll
        for (int r = 0; r < 8; ++r) {
            const float x0 = base[(r     ) * PITCH + p];
            const float x1 = base[(r +  8) * PITCH + p];
            const float x2 = base[(r + 16) * PITCH + p];
            const float x3 = base[(r + 24) * PITCH + p];
            s0 = fmaf(x0, x0, s0); s1 = fmaf(x1, x1, s1);
            s2 = fmaf(x2, x2, s2); s3 = fmaf(x3, x3, s3);
        }
        ivv[half][p] = 1.f / (sqrtf((s0 + s1) + (s2 + s3)) + 1e-8f);
    }
    __syncthreads();

    // ---- Normalize and convert to tf32 in place ----
#pragma unroll
    for (int s = tid; s < 2048; s += TH1) {
        const int row = s >> 5;              // 0..63
        const int q = s & 31;
        const float4 w = *(const float4*)&ivv[row >> 5][4 * q];
        float4 v = *(float4*)&sU[row * PITCH + 4 * q];
        v.x *= w.x; v.y *= w.y; v.z *= w.z; v.w *= w.w;
        unsigned t0, t1, t2, t3;
        asm("cvt.rna.tf32.f32 %0, %1;" : "=r"(t0) : "f"(v.x));
        asm("cvt.rna.tf32.f32 %0, %1;" : "=r"(t1) : "f"(v.y));
        asm("cvt.rna.tf32.f32 %0, %1;" : "=r"(t2) : "f"(v.z));
        asm("cvt.rna.tf32.f32 %0, %1;" : "=r"(t3) : "f"(v.w));
        uint4 o = {t0, t1, t2, t3};
        *(uint4*)&sU[row * PITCH + 4 * q] = o;
    }
    __syncthreads();

    // ---- Tensor-core Gram: G = U * U^T, 64x64 via m16n8k8 tf32 ----
    const int wrp  = tid >> 5;
    const int lane = tid & 31;
    const int i0   = 16 * (wrp & 3);
    const int j0   = 32 * (wrp >> 2);
    const int gi   = lane >> 2;              // 0..7
    const int gk   = lane & 3;               // 0..3

    float acc[4][4];
#pragma unroll
    for (int t = 0; t < 4; ++t)
#pragma unroll
        for (int r = 0; r < 4; ++r) acc[t][r] = 0.f;

    const float* aR0 = sU + (i0 + gi) * PITCH + gk;        // A rows gi, gi+8
    const float* aR1 = aR0 + 8 * PITCH;

#pragma unroll
    for (int ks = 0; ks < TPB / 8; ++ks) {
        const int kk = 8 * ks;
        unsigned a0 = __float_as_uint(aR0[kk]);
        unsigned a1 = __float_as_uint(aR1[kk]);
        unsigned a2 = __float_as_uint(aR0[kk + 4]);
        unsigned a3 = __float_as_uint(aR1[kk + 4]);
#pragma unroll
        for (int nt = 0; nt < 4; ++nt) {
            const float* bB = sU + (j0 + 8 * nt + gi) * PITCH + gk;
            unsigned b0 = __float_as_uint(bB[kk]);
            unsigned b1 = __float_as_uint(bB[kk + 4]);
            asm("mma.sync.aligned.m16n8k8.row.col.f32.tf32.tf32.f32 "
                "{%0,%1,%2,%3}, {%4,%5,%6,%7}, {%8,%9}, {%0,%1,%2,%3};"
                : "+f"(acc[nt][0]), "+f"(acc[nt][1]), "+f"(acc[nt][2]), "+f"(acc[nt][3])
                : "r"(a0), "r"(a1), "r"(a2), "r"(a3), "r"(b0), "r"(b1));
        }
    }

    // ---- Fire-and-forget v2 reductions into replicated slot ----
    const int rep = blk & (NREP - 1);
    float* dstA = g_acc + (size_t)(rep * NI + n) * 4096;
#pragma unroll
    for (int nt = 0; nt < 4; ++nt) {
        const int jcol = j0 + 8 * nt + 2 * gk;
        float* d0 = &dstA[(i0 + gi    ) * 64 + jcol];
        float* d1 = &dstA[(i0 + gi + 8) * 64 + jcol];
        asm volatile("red.global.add.v2.f32 [%0], {%1,%2};"
                     :: "l"(d0), "f"(acc[nt][0]), "f"(acc[nt][1]) : "memory");
        asm volatile("red.global.add.v2.f32 [%0], {%1,%2};"
                     :: "l"(d1), "f"(acc[nt][2]), "f"(acc[nt][3]) : "memory");
    }

    // ---- Per-item ticket: last block of each item runs the item epilogue ----
    __threadfence();
    if (tid == 0) s_pos = atomicAdd(&g_tick[n], 1u);
    __syncthreads();
    if (s_pos != BPI - 1) return;

    // Item epilogue (256 threads): sum 8 replicas per element (L2-hot),
    // zero them for the next replay, weight (+1 diag blocks, -1 cross), square.
    float local = 0.f;
#pragma unroll
    for (int e = tid; e < 4096; e += TH1) {
        float v = 0.f;
#pragma unroll
        for (int r = 0; r < NREP; ++r)
            v += g_acc[(size_t)(r * NI + n) * 4096 + e];
#pragma unroll
        for (int r = 0; r < NREP; ++r)
            g_acc[(size_t)(r * NI + n) * 4096 + e] = 0.f;
        const int i = e >> 6, j = e & 63;
        const float w = (((i ^ j) & 32) == 0) ? 1.f : -1.f;
        local = fmaf(w * v, v, local);
    }
#pragma unroll
    for (int off = 16; off > 0; off >>= 1)
        local += __shfl_down_sync(0xffffffffu, local, off);

    __shared__ float wsum[8];
    if ((tid & 31) == 0) wsum[tid >> 5] = local;
    __syncthreads();

    if (tid == 0) {
        float tot = 0.f;
#pragma unroll
        for (int k = 0; k < 8; ++k) tot += wsum[k];
        g_item[n] = tot;
        __threadfence();
        // Final ticket: the 8th item epilogue assembles the loss.
        if (atomicAdd(&g_tick[NI], 1u) == NI - 1) {
            float s = 0.f;
#pragma unroll
            for (int k = 0; k < NI; ++k) s += __ldcg(&g_item[k]);
            // loss = total / (HW^2) / (B*L)
            out[0] = s * (1.f / (16777216.f * 8.f));
            // Reset tickets for the next graph replay.
#pragma unroll
            for (int k = 0; k <= NI; ++k) g_tick[k] = 0u;
        }
    }
}

extern "C" void kernel_launch(void* const* d_in, const int* in_sizes, int n_in,
                              void* d_out, int out_size) {
    const float* S = (const float*)d_in[0];
    const float* T = (const float*)d_in[1];
    (void)in_sizes; (void)n_in; (void)out_size;

    dim3 g1(BPI, NI);
    k_fused<<<g1, TH1>>>(S, T, (float*)d_out);
}